// round 1
// baseline (speedup 1.0000x reference)
#include <cuda_runtime.h>
#include <cuda_bf16.h>
#include <math.h>

// Problem constants (shapes fixed by the dataset)
#define MAXN 100000
#define MAXG 1000
#define D1 3
#define H  50   // D2
#define D3 15
#define D5 10
#define NC 6
#define EPS 1e-5f

#define TPB 256

// -------- scratch (device globals; no allocation allowed) --------
__device__ float g_x2sum[MAXN * 16];   // per-node: 15 msg sums + count
__device__ float g_gsum[MAXG * 16];    // per-graph: 15 node-mean sums + count
__device__ float g_z[MAXG * D5];       // pre-BN activations
__device__ float g_zstat[2 * D5];      // col sums and sums of squares

// -------------------- zero scratch --------------------
__global__ void zero_kernel(int n_x2, int n_g) {
    int i = blockIdx.x * blockDim.x + threadIdx.x;
    int stride = gridDim.x * blockDim.x;
    for (int k = i; k < n_x2; k += stride) g_x2sum[k] = 0.f;
    for (int k = i; k < n_g;  k += stride) g_gsum[k]  = 0.f;
    if (i < 2 * D5) g_zstat[i] = 0.f;
}

__device__ __forceinline__ void red_add_v4(float* dst, float a, float b, float c, float d) {
    asm volatile("red.global.add.v4.f32 [%0], {%1,%2,%3,%4};"
                 :: "l"(dst), "f"(a), "f"(b), "f"(c), "f"(d) : "memory");
}

// -------------------- edge + node-message kernel --------------------
// Per edge: edge MLP (9->50->15), node MLP (18->50->15), scatter-add msg by row.
__global__ __launch_bounds__(TPB)
void edge_kernel(const float* __restrict__ x, const int* __restrict__ ei,
                 const float* __restrict__ ea,
                 const float* __restrict__ ew1, const float* __restrict__ eb1,
                 const float* __restrict__ ew2, const float* __restrict__ eb2,
                 const float* __restrict__ nw1, const float* __restrict__ nb1,
                 const float* __restrict__ nw2, const float* __restrict__ nb2,
                 int E)
{
    // shared weight cache: ew1 450 | eb1 50 | ew2 750 | eb2 16 | nw1 900 | nb1 50 | nw2 750 | nb2 16
    __shared__ float s[450 + 50 + 750 + 16 + 900 + 50 + 750 + 16];
    float* sew1 = s;
    float* seb1 = sew1 + 450;
    float* sew2 = seb1 + 50;
    float* seb2 = sew2 + 750;
    float* snw1 = seb2 + 16;
    float* snb1 = snw1 + 900;
    float* snw2 = snb1 + 50;
    float* snb2 = snw2 + 750;

    int tid = threadIdx.x;
    for (int i = tid; i < 450; i += TPB) sew1[i] = ew1[i];
    for (int i = tid; i < 50;  i += TPB) seb1[i] = eb1[i];
    for (int i = tid; i < 750; i += TPB) sew2[i] = ew2[i];
    for (int i = tid; i < 15;  i += TPB) seb2[i] = eb2[i];
    for (int i = tid; i < 900; i += TPB) snw1[i] = nw1[i];
    for (int i = tid; i < 50;  i += TPB) snb1[i] = nb1[i];
    for (int i = tid; i < 750; i += TPB) snw2[i] = nw2[i];
    for (int i = tid; i < 15;  i += TPB) snb2[i] = nb2[i];
    __syncthreads();

    for (int e = blockIdx.x * TPB + tid; e < E; e += gridDim.x * TPB) {
        int r = ei[e];
        int c = ei[E + e];

        float xc0 = __ldg(&x[3 * c]);
        float xc1 = __ldg(&x[3 * c + 1]);
        float xc2 = __ldg(&x[3 * c + 2]);

        float in0[9];
        in0[0] = __ldg(&x[3 * r]);
        in0[1] = __ldg(&x[3 * r + 1]);
        in0[2] = __ldg(&x[3 * r + 2]);
        in0[3] = xc0; in0[4] = xc1; in0[5] = xc2;
        in0[6] = ea[3 * e]; in0[7] = ea[3 * e + 1]; in0[8] = ea[3 * e + 2];

        // edge MLP layer 1: 9 -> 50, ReLU
        float h[H];
        #pragma unroll
        for (int j = 0; j < H; j++) {
            float a = seb1[j];
            #pragma unroll
            for (int k = 0; k < 9; k++) a += in0[k] * sew1[k * H + j];
            h[j] = fmaxf(a, 0.f);
        }
        // edge MLP layer 2: 50 -> 15
        float e2[D3];
        #pragma unroll
        for (int j = 0; j < D3; j++) {
            float a = seb2[j];
            #pragma unroll
            for (int k = 0; k < H; k++) a += h[k] * sew2[k * D3 + j];
            e2[j] = a;
        }
        // node MLP layer 1: [x[col](3), e2(15)] -> 50, ReLU
        float g[H];
        #pragma unroll
        for (int j = 0; j < H; j++) {
            float a = snb1[j];
            a += xc0 * snw1[j];
            a += xc1 * snw1[H + j];
            a += xc2 * snw1[2 * H + j];
            #pragma unroll
            for (int k = 0; k < D3; k++) a += e2[k] * snw1[(3 + k) * H + j];
            g[j] = fmaxf(a, 0.f);
        }
        // node MLP layer 2: 50 -> 15
        float m[16];
        #pragma unroll
        for (int j = 0; j < D3; j++) {
            float a = snb2[j];
            #pragma unroll
            for (int k = 0; k < H; k++) a += g[k] * snw2[k * D3 + j];
            m[j] = a;
        }
        m[15] = 1.0f;  // count

        float* dst = g_x2sum + (size_t)r * 16;
        red_add_v4(dst,      m[0],  m[1],  m[2],  m[3]);
        red_add_v4(dst + 4,  m[4],  m[5],  m[6],  m[7]);
        red_add_v4(dst + 8,  m[8],  m[9],  m[10], m[11]);
        red_add_v4(dst + 12, m[12], m[13], m[14], m[15]);
    }
}

// -------------------- node finalize + graph scatter --------------------
__global__ void node_kernel(const int* __restrict__ batch, int N)
{
    int n = blockIdx.x * blockDim.x + threadIdx.x;
    if (n >= N) return;
    const float* sp = g_x2sum + (size_t)n * 16;
    float inv = 1.f / fmaxf(sp[15], 1.f);
    float v[16];
    #pragma unroll
    for (int j = 0; j < D3; j++) v[j] = sp[j] * inv;
    v[15] = 1.0f;
    float* dst = g_gsum + (size_t)batch[n] * 16;
    red_add_v4(dst,      v[0],  v[1],  v[2],  v[3]);
    red_add_v4(dst + 4,  v[4],  v[5],  v[6],  v[7]);
    red_add_v4(dst + 8,  v[8],  v[9],  v[10], v[11]);
    red_add_v4(dst + 12, v[12], v[13], v[14], v[15]);
}

// -------------------- global MLP + fc1 + BN stats --------------------
__global__ void global_kernel(const float* __restrict__ u,
                              const float* __restrict__ gw1, const float* __restrict__ gb1,
                              const float* __restrict__ gw2, const float* __restrict__ gb2,
                              const float* __restrict__ f1w, const float* __restrict__ f1b,
                              int G)
{
    int gi = blockIdx.x * blockDim.x + threadIdx.x;
    if (gi >= G) return;
    float gin[16];
    gin[0] = u[gi];
    const float* sp = g_gsum + (size_t)gi * 16;
    float inv = 1.f / fmaxf(sp[15], 1.f);
    #pragma unroll
    for (int j = 0; j < D3; j++) gin[1 + j] = sp[j] * inv;

    float h[H];
    #pragma unroll
    for (int j = 0; j < H; j++) {
        float a = gb1[j];
        #pragma unroll
        for (int k = 0; k < 16; k++) a += gin[k] * gw1[k * H + j];
        h[j] = fmaxf(a, 0.f);
    }
    float u2[D3];
    #pragma unroll
    for (int j = 0; j < D3; j++) {
        float a = gb2[j];
        #pragma unroll
        for (int k = 0; k < H; k++) a += h[k] * gw2[k * D3 + j];
        u2[j] = a;
    }
    #pragma unroll
    for (int j = 0; j < D5; j++) {
        float a = f1b[j];
        #pragma unroll
        for (int k = 0; k < D3; k++) a += u2[k] * f1w[k * D5 + j];
        g_z[gi * D5 + j] = a;
        atomicAdd(&g_zstat[j], a);
        atomicAdd(&g_zstat[D5 + j], a * a);
    }
}

// -------------------- BN + ReLU + fc2 + log_softmax --------------------
__global__ void head_kernel(const float* __restrict__ bn_g, const float* __restrict__ bn_b,
                            const float* __restrict__ f2w, const float* __restrict__ f2b,
                            float* __restrict__ out, int G)
{
    int gi = blockIdx.x * blockDim.x + threadIdx.x;
    if (gi >= G) return;
    float invG = 1.f / (float)G;
    float zr[D5];
    #pragma unroll
    for (int j = 0; j < D5; j++) {
        float mean = g_zstat[j] * invG;
        float var  = g_zstat[D5 + j] * invG - mean * mean;
        float zn = (g_z[gi * D5 + j] - mean) * rsqrtf(var + EPS) * bn_g[j] + bn_b[j];
        zr[j] = fmaxf(zn, 0.f);
    }
    float lg[NC];
    float mx = -1e30f;
    #pragma unroll
    for (int j = 0; j < NC; j++) {
        float a = f2b[j];
        #pragma unroll
        for (int k = 0; k < D5; k++) a += zr[k] * f2w[k * NC + j];
        lg[j] = a;
        mx = fmaxf(mx, a);
    }
    float se = 0.f;
    #pragma unroll
    for (int j = 0; j < NC; j++) se += expf(lg[j] - mx);
    float lse = mx + logf(se);
    #pragma unroll
    for (int j = 0; j < NC; j++) out[gi * NC + j] = lg[j] - lse;
}

// -------------------- launch --------------------
extern "C" void kernel_launch(void* const* d_in, const int* in_sizes, int n_in,
                              void* d_out, int out_size)
{
    const float* x     = (const float*)d_in[0];
    const int*   ei    = (const int*)  d_in[1];
    const float* ea    = (const float*)d_in[2];
    const float* u     = (const float*)d_in[3];
    const int*   batch = (const int*)  d_in[4];
    const float* ew1 = (const float*)d_in[5];
    const float* eb1 = (const float*)d_in[6];
    const float* ew2 = (const float*)d_in[7];
    const float* eb2 = (const float*)d_in[8];
    const float* nw1 = (const float*)d_in[9];
    const float* nb1 = (const float*)d_in[10];
    const float* nw2 = (const float*)d_in[11];
    const float* nb2 = (const float*)d_in[12];
    const float* gw1 = (const float*)d_in[13];
    const float* gb1 = (const float*)d_in[14];
    const float* gw2 = (const float*)d_in[15];
    const float* gb2 = (const float*)d_in[16];
    const float* f1w = (const float*)d_in[17];
    const float* f1b = (const float*)d_in[18];
    const float* bn_g = (const float*)d_in[19];
    const float* bn_b = (const float*)d_in[20];
    const float* f2w = (const float*)d_in[21];
    const float* f2b = (const float*)d_in[22];
    float* out = (float*)d_out;

    int N = in_sizes[0] / 3;
    int E = in_sizes[1] / 2;
    int G = in_sizes[3];

    // 1. zero scratch
    {
        int n_x2 = N * 16, n_g = G * 16;
        int blocks = (n_x2 + TPB - 1) / TPB;
        if (blocks > 4096) blocks = 4096;
        zero_kernel<<<blocks, TPB>>>(n_x2, n_g);
    }
    // 2. edge + node-message + scatter
    {
        int blocks = 152 * 12;
        int need = (E + TPB - 1) / TPB;
        if (need < blocks) blocks = need;
        edge_kernel<<<blocks, TPB>>>(x, ei, ea, ew1, eb1, ew2, eb2,
                                     nw1, nb1, nw2, nb2, E);
    }
    // 3. node finalize -> graph scatter
    node_kernel<<<(N + TPB - 1) / TPB, TPB>>>(batch, N);
    // 4. global MLP + fc1 + BN stats
    global_kernel<<<(G + TPB - 1) / TPB, TPB>>>(u, gw1, gb1, gw2, gb2, f1w, f1b, G);
    // 5. BN + head + log_softmax
    head_kernel<<<(G + TPB - 1) / TPB, TPB>>>(bn_g, bn_b, f2w, f2b, out, G);
}

// round 3
// speedup vs baseline: 1.0687x; 1.0687x over previous
#include <cuda_runtime.h>
#include <cuda_bf16.h>
#include <math.h>

#define MAXN 100000
#define MAXG 1000
#define D1 3
#define H  50
#define D3 15
#define D5 10
#define NC 6
#define EPS 1e-5f

#define TPB 256

typedef unsigned long long ull;

// -------- scratch (device globals) --------
__device__ float g_x2sum[MAXN * 16];   // per-node: 15 msg sums + count
__device__ float g_gsum[MAXG * 16];    // per-graph: 15 node-mean sums + count
__device__ float g_z[MAXG * D5];       // pre-BN activations
__device__ float g_zstat[2 * D5];      // col sums and sums of squares

// -------- packed f32x2 helpers --------
__device__ __forceinline__ ull pack2(float a, float b) {
    ull r;
    asm("mov.b64 %0, {%1,%2};" : "=l"(r) : "f"(a), "f"(b));
    return r;
}
__device__ __forceinline__ void unpack2(ull v, float& a, float& b) {
    asm("mov.b64 {%0,%1}, %2;" : "=f"(a), "=f"(b) : "l"(v));
}
__device__ __forceinline__ void ffma2(ull& d, ull a, ull b) {
    asm("fma.rn.f32x2 %0, %1, %2, %0;" : "+l"(d) : "l"(a), "l"(b));
}
__device__ __forceinline__ ull relu2(ull v) {
    float a, b; unpack2(v, a, b);
    return pack2(fmaxf(a, 0.f), fmaxf(b, 0.f));
}

__device__ __forceinline__ void red_add_v4(float* dst, float a, float b, float c, float d) {
    asm volatile("red.global.add.v4.f32 [%0], {%1,%2,%3,%4};"
                 :: "l"(dst), "f"(a), "f"(b), "f"(c), "f"(d) : "memory");
}

// -------------------- zero scratch --------------------
__global__ void zero_kernel(int n_x2, int n_g) {
    int i = blockIdx.x * blockDim.x + threadIdx.x;
    int stride = gridDim.x * blockDim.x;
    for (int k = i; k < n_x2; k += stride) g_x2sum[k] = 0.f;
    for (int k = i; k < n_g;  k += stride) g_gsum[k]  = 0.f;
    if (i < 2 * D5) g_zstat[i] = 0.f;
}

// -------------------- edge + node-message kernel (2 edges/thread, f32x2) ---
__global__ __launch_bounds__(TPB, 1)
void edge_kernel(const float* __restrict__ x, const int* __restrict__ ei,
                 const float* __restrict__ ea,
                 const float* __restrict__ ew1, const float* __restrict__ eb1,
                 const float* __restrict__ ew2, const float* __restrict__ eb2,
                 const float* __restrict__ nw1, const float* __restrict__ nb1,
                 const float* __restrict__ nw2, const float* __restrict__ nb2,
                 int E)
{
    // duplicated-pair weights in shared: value in both 32-bit lanes
    __shared__ ull sew1[450], seb1[H], sew2[750], seb2[D3];
    __shared__ ull snw1[900], snb1[H], snw2[750], snb2[D3];

    int tid = threadIdx.x;
    for (int i = tid; i < 450; i += TPB) { float w = ew1[i]; sew1[i] = pack2(w, w); }
    for (int i = tid; i < H;   i += TPB) { float w = eb1[i]; seb1[i] = pack2(w, w); }
    for (int i = tid; i < 750; i += TPB) { float w = ew2[i]; sew2[i] = pack2(w, w); }
    for (int i = tid; i < D3;  i += TPB) { float w = eb2[i]; seb2[i] = pack2(w, w); }
    for (int i = tid; i < 900; i += TPB) { float w = nw1[i]; snw1[i] = pack2(w, w); }
    for (int i = tid; i < H;   i += TPB) { float w = nb1[i]; snb1[i] = pack2(w, w); }
    for (int i = tid; i < 750; i += TPB) { float w = nw2[i]; snw2[i] = pack2(w, w); }
    for (int i = tid; i < D3;  i += TPB) { float w = nb2[i]; snb2[i] = pack2(w, w); }
    __syncthreads();

    int npairs = (E + 1) >> 1;
    for (int p = blockIdx.x * TPB + tid; p < npairs; p += gridDim.x * TPB) {
        int e0 = 2 * p;
        int e1 = e0 + 1;
        bool has2 = (e1 < E);
        if (!has2) e1 = e0;

        int r0 = ei[e0], r1 = ei[e1];
        int c0 = ei[E + e0], c1 = ei[E + e1];

        ull in[9];
        in[0] = pack2(__ldg(&x[3 * r0]),     __ldg(&x[3 * r1]));
        in[1] = pack2(__ldg(&x[3 * r0 + 1]), __ldg(&x[3 * r1 + 1]));
        in[2] = pack2(__ldg(&x[3 * r0 + 2]), __ldg(&x[3 * r1 + 2]));
        in[3] = pack2(__ldg(&x[3 * c0]),     __ldg(&x[3 * c1]));
        in[4] = pack2(__ldg(&x[3 * c0 + 1]), __ldg(&x[3 * c1 + 1]));
        in[5] = pack2(__ldg(&x[3 * c0 + 2]), __ldg(&x[3 * c1 + 2]));
        in[6] = pack2(ea[3 * e0],     ea[3 * e1]);
        in[7] = pack2(ea[3 * e0 + 1], ea[3 * e1 + 1]);
        in[8] = pack2(ea[3 * e0 + 2], ea[3 * e1 + 2]);

        // edge MLP layer 1: 9 -> 50, ReLU
        ull h[H];
        #pragma unroll
        for (int j = 0; j < H; j++) h[j] = seb1[j];
        #pragma unroll
        for (int k = 0; k < 9; k++)
            #pragma unroll
            for (int j = 0; j < H; j++) ffma2(h[j], in[k], sew1[k * H + j]);
        #pragma unroll
        for (int j = 0; j < H; j++) h[j] = relu2(h[j]);

        // edge MLP layer 2: 50 -> 15
        ull e2[D3];
        #pragma unroll
        for (int j = 0; j < D3; j++) e2[j] = seb2[j];
        #pragma unroll
        for (int k = 0; k < H; k++)
            #pragma unroll
            for (int j = 0; j < D3; j++) ffma2(e2[j], h[k], sew2[k * D3 + j]);

        // node MLP layer 1: [x[col](3), e2(15)] -> 50, ReLU
        ull g[H];
        #pragma unroll
        for (int j = 0; j < H; j++) g[j] = snb1[j];
        #pragma unroll
        for (int k = 0; k < 3; k++)
            #pragma unroll
            for (int j = 0; j < H; j++) ffma2(g[j], in[3 + k], snw1[k * H + j]);
        #pragma unroll
        for (int k = 0; k < D3; k++)
            #pragma unroll
            for (int j = 0; j < H; j++) ffma2(g[j], e2[k], snw1[(3 + k) * H + j]);
        #pragma unroll
        for (int j = 0; j < H; j++) g[j] = relu2(g[j]);

        // node MLP layer 2: 50 -> 15
        ull m[D3];
        #pragma unroll
        for (int j = 0; j < D3; j++) m[j] = snb2[j];
        #pragma unroll
        for (int k = 0; k < H; k++)
            #pragma unroll
            for (int j = 0; j < D3; j++) ffma2(m[j], g[k], snw2[k * D3 + j]);

        float ma[16], mb[16];
        #pragma unroll
        for (int j = 0; j < D3; j++) unpack2(m[j], ma[j], mb[j]);
        ma[15] = 1.0f; mb[15] = 1.0f;

        float* d0 = g_x2sum + (size_t)r0 * 16;
        red_add_v4(d0,      ma[0],  ma[1],  ma[2],  ma[3]);
        red_add_v4(d0 + 4,  ma[4],  ma[5],  ma[6],  ma[7]);
        red_add_v4(d0 + 8,  ma[8],  ma[9],  ma[10], ma[11]);
        red_add_v4(d0 + 12, ma[12], ma[13], ma[14], ma[15]);
        if (has2) {
            float* d1 = g_x2sum + (size_t)r1 * 16;
            red_add_v4(d1,      mb[0],  mb[1],  mb[2],  mb[3]);
            red_add_v4(d1 + 4,  mb[4],  mb[5],  mb[6],  mb[7]);
            red_add_v4(d1 + 8,  mb[8],  mb[9],  mb[10], mb[11]);
            red_add_v4(d1 + 12, mb[12], mb[13], mb[14], mb[15]);
        }
    }
}

// -------------------- node finalize + graph scatter --------------------
__global__ void node_kernel(const int* __restrict__ batch, int N)
{
    int n = blockIdx.x * blockDim.x + threadIdx.x;
    if (n >= N) return;
    const float* sp = g_x2sum + (size_t)n * 16;
    float inv = 1.f / fmaxf(sp[15], 1.f);
    float v[16];
    #pragma unroll
    for (int j = 0; j < D3; j++) v[j] = sp[j] * inv;
    v[15] = 1.0f;
    float* dst = g_gsum + (size_t)batch[n] * 16;
    red_add_v4(dst,      v[0],  v[1],  v[2],  v[3]);
    red_add_v4(dst + 4,  v[4],  v[5],  v[6],  v[7]);
    red_add_v4(dst + 8,  v[8],  v[9],  v[10], v[11]);
    red_add_v4(dst + 12, v[12], v[13], v[14], v[15]);
}

// -------------------- global MLP + fc1 + BN stats (warp per graph) -------
__global__ __launch_bounds__(256)
void global_kernel(const float* __restrict__ u,
                   const float* __restrict__ gw1, const float* __restrict__ gb1,
                   const float* __restrict__ gw2, const float* __restrict__ gb2,
                   const float* __restrict__ f1w, const float* __restrict__ f1b,
                   int G)
{
    __shared__ float sh[8][52];
    __shared__ float su[8][16];
    int w = threadIdx.x >> 5;
    int lane = threadIdx.x & 31;
    int gi = blockIdx.x * 8 + w;
    if (gi >= G) return;

    float gin[16];
    gin[0] = u[gi];
    const float* sp = g_gsum + (size_t)gi * 16;
    float inv = 1.f / fmaxf(__ldg(&sp[15]), 1.f);
    #pragma unroll
    for (int j = 0; j < D3; j++) gin[1 + j] = __ldg(&sp[j]) * inv;

    // layer1: 16 -> 50, lanes cover j and j+32
    {
        int j = lane;
        float a = gb1[j];
        #pragma unroll
        for (int k = 0; k < 16; k++) a += gin[k] * gw1[k * H + j];
        sh[w][j] = fmaxf(a, 0.f);
        if (lane < H - 32) {
            int j2 = lane + 32;
            float a2 = gb1[j2];
            #pragma unroll
            for (int k = 0; k < 16; k++) a2 += gin[k] * gw1[k * H + j2];
            sh[w][j2] = fmaxf(a2, 0.f);
        }
    }
    __syncwarp();
    // layer2: 50 -> 15
    if (lane < D3) {
        float a = gb2[lane];
        #pragma unroll
        for (int k = 0; k < H; k++) a += sh[w][k] * gw2[k * D3 + lane];
        su[w][lane] = a;
    }
    __syncwarp();
    // fc1: 15 -> 10 + BN stats
    if (lane < D5) {
        float a = f1b[lane];
        #pragma unroll
        for (int k = 0; k < D3; k++) a += su[w][k] * f1w[k * D5 + lane];
        g_z[gi * D5 + lane] = a;
        atomicAdd(&g_zstat[lane], a);
        atomicAdd(&g_zstat[D5 + lane], a * a);
    }
}

// -------------------- BN + ReLU + fc2 + log_softmax --------------------
__global__ void head_kernel(const float* __restrict__ bn_g, const float* __restrict__ bn_b,
                            const float* __restrict__ f2w, const float* __restrict__ f2b,
                            float* __restrict__ out, int G)
{
    int gi = blockIdx.x * blockDim.x + threadIdx.x;
    if (gi >= G) return;
    float invG = 1.f / (float)G;
    float zr[D5];
    #pragma unroll
    for (int j = 0; j < D5; j++) {
        float mean = g_zstat[j] * invG;
        float var  = g_zstat[D5 + j] * invG - mean * mean;
        float zn = (g_z[gi * D5 + j] - mean) * rsqrtf(var + EPS) * bn_g[j] + bn_b[j];
        zr[j] = fmaxf(zn, 0.f);
    }
    float lg[NC];
    float mx = -1e30f;
    #pragma unroll
    for (int j = 0; j < NC; j++) {
        float a = f2b[j];
        #pragma unroll
        for (int k = 0; k < D5; k++) a += zr[k] * f2w[k * NC + j];
        lg[j] = a;
        mx = fmaxf(mx, a);
    }
    float se = 0.f;
    #pragma unroll
    for (int j = 0; j < NC; j++) se += expf(lg[j] - mx);
    float lse = mx + logf(se);
    #pragma unroll
    for (int j = 0; j < NC; j++) out[gi * NC + j] = lg[j] - lse;
}

// -------------------- launch --------------------
extern "C" void kernel_launch(void* const* d_in, const int* in_sizes, int n_in,
                              void* d_out, int out_size)
{
    const float* x     = (const float*)d_in[0];
    const int*   ei    = (const int*)  d_in[1];
    const float* ea    = (const float*)d_in[2];
    const float* u     = (const float*)d_in[3];
    const int*   batch = (const int*)  d_in[4];
    const float* ew1 = (const float*)d_in[5];
    const float* eb1 = (const float*)d_in[6];
    const float* ew2 = (const float*)d_in[7];
    const float* eb2 = (const float*)d_in[8];
    const float* nw1 = (const float*)d_in[9];
    const float* nb1 = (const float*)d_in[10];
    const float* nw2 = (const float*)d_in[11];
    const float* nb2 = (const float*)d_in[12];
    const float* gw1 = (const float*)d_in[13];
    const float* gb1 = (const float*)d_in[14];
    const float* gw2 = (const float*)d_in[15];
    const float* gb2 = (const float*)d_in[16];
    const float* f1w = (const float*)d_in[17];
    const float* f1b = (const float*)d_in[18];
    const float* bn_g = (const float*)d_in[19];
    const float* bn_b = (const float*)d_in[20];
    const float* f2w = (const float*)d_in[21];
    const float* f2b = (const float*)d_in[22];
    float* out = (float*)d_out;

    int N = in_sizes[0] / 3;
    int E = in_sizes[1] / 2;
    int G = in_sizes[3];

    {
        int n_x2 = N * 16, n_g = G * 16;
        int blocks = (n_x2 + TPB - 1) / TPB;
        if (blocks > 4096) blocks = 4096;
        zero_kernel<<<blocks, TPB>>>(n_x2, n_g);
    }
    {
        int npairs = (E + 1) / 2;
        int blocks = 152 * 4;
        int need = (npairs + TPB - 1) / TPB;
        if (need < blocks) blocks = need;
        edge_kernel<<<blocks, TPB>>>(x, ei, ea, ew1, eb1, ew2, eb2,
                                     nw1, nb1, nw2, nb2, E);
    }
    node_kernel<<<(N + TPB - 1) / TPB, TPB>>>(batch, N);
    global_kernel<<<(G + 7) / 8, 256>>>(u, gw1, gb1, gw2, gb2, f1w, f1b, G);
    head_kernel<<<(G + TPB - 1) / TPB, TPB>>>(bn_g, bn_b, f2w, f2b, out, G);
}